// round 7
// baseline (speedup 1.0000x reference)
#include <cuda_runtime.h>
#include <cuda_bf16.h>
#include <cstdint>

#define N_ROWS 32768
#define N_CODES 8192
#define DIM 64
#define HW 4096
#define ZB 262144
#define NELEM 2097152
#define NCH 64
#define TCODES 128
#define CAP (1 << 22)
#define IMARGIN 1200        // int-dot margin (scale 2^20): ~12 sigma of quant error

__device__ int                g_idx[N_ROWS];
__device__ float              g_A[N_ROWS];
__device__ float              g_B[N_CODES];
__device__ float              g_zT[N_ROWS * DIM];
__device__ signed char        g_z8[N_ROWS * DIM];
__device__ signed char        g_e8[N_CODES * DIM];
__device__ unsigned long long g_key[N_ROWS];
__device__ unsigned int       g_cand[CAP];
__device__ int                g_cnt;
__device__ double             g_partial[2048];

__device__ __forceinline__ uint32_t smem_u32(const void* p) {
    uint32_t a;
    asm("{ .reg .u64 t; cvta.to.shared.u64 t, %1; cvt.u32.u64 %0, t; }" : "=r"(a) : "l"(p));
    return a;
}
__device__ __forceinline__ void cp_async16(uint32_t dst, const void* src) {
    asm volatile("cp.async.cg.shared.global [%0], [%1], 16;" :: "r"(dst), "l"(src) : "memory");
}
#define CP_COMMIT() asm volatile("cp.async.commit_group;" ::: "memory")
#define CP_WAIT1()  asm volatile("cp.async.wait_group 1;" ::: "memory")
#define CP_WAIT0()  asm volatile("cp.async.wait_group 0;" ::: "memory")

__device__ __forceinline__ void imma16832(int& c0, int& c1, int& c2, int& c3,
                                          uint32_t a0, uint32_t a1, uint32_t a2, uint32_t a3,
                                          uint32_t b0, uint32_t b1) {
    asm volatile(
        "mma.sync.aligned.m16n8k32.row.col.s32.s8.s8.s32 "
        "{%0,%1,%2,%3}, {%4,%5,%6,%7}, {%8,%9}, {%0,%1,%2,%3};"
        : "+r"(c0), "+r"(c1), "+r"(c2), "+r"(c3)
        : "r"(a0), "r"(a1), "r"(a2), "r"(a3), "r"(b0), "r"(b1));
}
__device__ __forceinline__ void ldmatrix_x4(uint32_t& r0, uint32_t& r1, uint32_t& r2,
                                            uint32_t& r3, uint32_t addr) {
    asm volatile("ldmatrix.sync.aligned.m8n8.x4.shared.b16 {%0,%1,%2,%3}, [%4];"
                 : "=r"(r0), "=r"(r1), "=r"(r2), "=r"(r3) : "r"(addr));
}

// ---------------------------------------------------------------------------
// Transpose z -> zT (f32), z8 (s8, x16), A = ||z||^2 (ascending-c fma chain)
// ---------------------------------------------------------------------------
__global__ void vq_transpose(const float* __restrict__ z) {
    __shared__ float sm[64][65];
    int b = blockIdx.x >> 6;
    int hw0 = (blockIdx.x & 63) << 6;
    int cc = threadIdx.x >> 6, hh = threadIdx.x & 63;
    const float* zb = z + b * ZB + hw0;
#pragma unroll
    for (int cq = 0; cq < 16; cq++) {
        int c = cq * 4 + cc;
        sm[hh][c] = zb[c * HW + hh];
    }
    __syncthreads();
#pragma unroll
    for (int rq = 0; rq < 16; rq++) {
        int r = rq * 4 + cc;
        int n = b * 4096 + hw0 + r;
        float v = sm[r][hh];
        g_zT[n * DIM + hh] = v;
        int q8 = __float2int_rn(v * 16.0f);
        q8 = max(-127, min(127, q8));
        g_z8[n * DIM + hh] = (signed char)q8;
    }
    if (threadIdx.x < 64) {
        int r = threadIdx.x;
        float s = 0.f;
#pragma unroll
        for (int c = 0; c < DIM; c++) s = __fmaf_rn(sm[r][c], sm[r][c], s);
        g_A[b * 4096 + hw0 + r] = s;
    }
}

__global__ void vq_prep(const float* __restrict__ emb) {
    int t = blockIdx.x * blockDim.x + threadIdx.x;
    if (t < N_CODES * DIM) {
        int q8 = __float2int_rn(emb[t] * 65536.0f);
        q8 = max(-127, min(127, q8));
        g_e8[t] = (signed char)q8;
    }
    if (t < N_ROWS) g_key[t] = 0xFFFFFFFFFFFFFFFFull;
    if (t == 0) g_cnt = 0;
    if (t < N_CODES) {
        const float4* ep = (const float4*)(emb + t * DIM);
        float s = 0.f;
#pragma unroll
        for (int i = 0; i < 16; i++) {
            float4 v = ep[i];
            s = __fmaf_rn(v.x, v.x, s);
            s = __fmaf_rn(v.y, v.y, s);
            s = __fmaf_rn(v.z, v.z, s);
            s = __fmaf_rn(v.w, v.w, s);
        }
        g_B[t] = s;
    }
}

// ---------------------------------------------------------------------------
// Filter: int8 IMMA dots (exact in int domain) + running-max collection.
// CTA 256 thr / 8 warps / 128 rows; warp = 16 rows x 128 codes per chunk.
// e smem in 4 seg-planes (s*2048 + c*16): ldmatrix rows are consecutive 16B.
// ---------------------------------------------------------------------------
#define SMEM_MMA (2 * 8192)   // double-buffered 8KB e tiles

__global__ __launch_bounds__(256, 2) void vq_mma(void) {
    extern __shared__ char smc[];
    uint32_t sb = smem_u32(smc);
    int tid = threadIdx.x;
    int wid = tid >> 5, lane = tid & 31;
    int row0 = blockIdx.x * 128;
    int g = lane >> 2, q = lane & 3;

    int rw = row0 + wid * 16;
    int row_a = rw + g, row_b = row_a + 8;

    // A fragments for K=64: 2 MMAs x 4 regs (rows row_a/row_b, 4-byte k-quads)
    uint32_t a[2][4];
    {
        const char* pa = (const char*)(g_z8 + row_a * DIM + q * 4);
        const char* pb = (const char*)(g_z8 + row_b * DIM + q * 4);
#pragma unroll
        for (int m = 0; m < 2; m++) {
            a[m][0] = *(const uint32_t*)(pa + m * 32);
            a[m][1] = *(const uint32_t*)(pb + m * 32);
            a[m][2] = *(const uint32_t*)(pa + m * 32 + 16);
            a[m][3] = *(const uint32_t*)(pb + m * 32 + 16);
        }
    }

    // ldmatrix lane address: plane = lane>>3 (seg), row = code tile + (lane&7)
    uint32_t lplane = (uint32_t)(lane >> 3) * 2048;
    uint32_t lrow16 = (uint32_t)(lane & 7) * 16;

    // prefetch chunks 0,1: 512 segs each; seg sid -> global sid*16,
    // smem plane (sid&3)*2048 + (sid>>2)*16
#pragma unroll
    for (int pc = 0; pc < 2; pc++) {
#pragma unroll
        for (int i = 0; i < 2; i++) {
            int sid = tid + i * 256;
            uint32_t dst = sb + pc * 8192 + (uint32_t)(sid & 3) * 2048 + (uint32_t)(sid >> 2) * 16;
            cp_async16(dst, g_e8 + pc * TCODES * DIM + sid * 16);
        }
        CP_COMMIT();
    }

    int run0 = 0x80000000, run1 = 0x80000000;

    for (int c = 0; c < NCH; c++) {
        if (c < NCH - 1) CP_WAIT1(); else CP_WAIT0();
        __syncthreads();

        uint32_t ebase = sb + (c & 1) * 8192 + lplane + lrow16;
        int acc[16][4];

#pragma unroll
        for (int t = 0; t < 16; t++) {
            uint32_t b0, b1, b2, b3;
            ldmatrix_x4(b0, b1, b2, b3, ebase + (uint32_t)t * 128);
            int c0 = 0, c1 = 0, c2 = 0, c3 = 0;
            imma16832(c0, c1, c2, c3, a[0][0], a[0][1], a[0][2], a[0][3], b0, b1);
            imma16832(c0, c1, c2, c3, a[1][0], a[1][1], a[1][2], a[1][3], b2, b3);
            acc[t][0] = c0; acc[t][1] = c1; acc[t][2] = c2; acc[t][3] = c3;
        }

        __syncthreads();
        if (c + 2 < NCH) {
#pragma unroll
            for (int i = 0; i < 2; i++) {
                int sid = tid + i * 256;
                uint32_t dst = sb + (c & 1) * 8192 + (uint32_t)(sid & 3) * 2048 + (uint32_t)(sid >> 2) * 16;
                cp_async16(dst, g_e8 + (c + 2) * TCODES * DIM + sid * 16);
            }
            CP_COMMIT();
        }

        // per-row chunk max (int)
        int m0 = 0x80000000, m1 = 0x80000000;
#pragma unroll
        for (int t = 0; t < 16; t++) {
            m0 = max(m0, max(acc[t][0], acc[t][1]));
            m1 = max(m1, max(acc[t][2], acc[t][3]));
        }
        m0 = max(m0, __shfl_xor_sync(0xffffffffu, m0, 1));
        m0 = max(m0, __shfl_xor_sync(0xffffffffu, m0, 2));
        m1 = max(m1, __shfl_xor_sync(0xffffffffu, m1, 1));
        m1 = max(m1, __shfl_xor_sync(0xffffffffu, m1, 2));
        run0 = max(run0, m0);
        run1 = max(run1, m1);
        int thr0 = run0 - IMARGIN, thr1 = run1 - IMARGIN;

        bool anyc = (m0 >= thr0) || (m1 >= thr1);
        if (!__any_sync(0xffffffffu, anyc)) continue;

        int cntl = 0;
#pragma unroll
        for (int t = 0; t < 16; t++) {
            cntl += (acc[t][0] >= thr0);
            cntl += (acc[t][1] >= thr0);
            cntl += (acc[t][2] >= thr1);
            cntl += (acc[t][3] >= thr1);
        }
        int pre = cntl;
#pragma unroll
        for (int o = 1; o < 32; o <<= 1) {
            int v = __shfl_up_sync(0xffffffffu, pre, o);
            if (lane >= o) pre += v;
        }
        int total = __shfl_sync(0xffffffffu, pre, 31);
        int base = 0;
        if (lane == 31 && total) base = atomicAdd(&g_cnt, total);
        base = __shfl_sync(0xffffffffu, base, 31);
        int pos = base + pre - cntl;

        if (cntl) {
            int j0 = c * TCODES + q * 2;
#pragma unroll
            for (int t = 0; t < 16; t++) {
                int j = j0 + t * 8;
                if (acc[t][0] >= thr0) { if (pos < CAP) g_cand[pos] = ((unsigned)row_a << 13) | (unsigned)j; pos++; }
                if (acc[t][1] >= thr0) { if (pos < CAP) g_cand[pos] = ((unsigned)row_a << 13) | (unsigned)(j + 1); pos++; }
                if (acc[t][2] >= thr1) { if (pos < CAP) g_cand[pos] = ((unsigned)row_b << 13) | (unsigned)j; pos++; }
                if (acc[t][3] >= thr1) { if (pos < CAP) g_cand[pos] = ((unsigned)row_b << 13) | (unsigned)(j + 1); pos++; }
            }
        }
    }
}

// ---------------------------------------------------------------------------
// Exact recheck: reference-matching fp32 d via float4 loads (ascending chain)
// ---------------------------------------------------------------------------
__global__ void vq_exact(const float* __restrict__ emb) {
    int cnt = g_cnt;
    if (cnt > CAP) cnt = CAP;
    for (int i = blockIdx.x * blockDim.x + threadIdx.x; i < cnt; i += gridDim.x * blockDim.x) {
        unsigned u = g_cand[i];
        int n = u >> 13;
        int j = u & 8191;
        const float4* zr = (const float4*)(g_zT + n * DIM);
        const float4* er = (const float4*)(emb + j * DIM);
        float dot = 0.f;
#pragma unroll
        for (int cc = 0; cc < 16; cc++) {
            float4 av = zr[cc];
            float4 bv = er[cc];
            dot = __fmaf_rn(av.x, bv.x, dot);
            dot = __fmaf_rn(av.y, bv.y, dot);
            dot = __fmaf_rn(av.z, bv.z, dot);
            dot = __fmaf_rn(av.w, bv.w, dot);
        }
        float d = __fsub_rn(__fadd_rn(g_A[n], g_B[j]), __fmul_rn(2.0f, dot));
        unsigned long long key = ((unsigned long long)__float_as_uint(d) << 13) | (unsigned)j;
        atomicMin(&g_key[n], key);
    }
}

__global__ void vq_finalize(float* __restrict__ outF) {
    int t = blockIdx.x * blockDim.x + threadIdx.x;
    if (t < N_ROWS) {
        int j = (int)(g_key[t] & 8191ull);
        g_idx[t] = j;
        outF[1 + NELEM + t] = (float)j;
    }
}

__global__ void vq_out(const float* __restrict__ z, const float* __restrict__ emb,
                       float* __restrict__ outF) {
    int t = blockIdx.x * 1024 + threadIdx.x;
    int c = (t >> 12) & 63;
    int n = ((t >> 18) << 12) | (t & 4095);
    int idx = g_idx[n];
    float zv = z[t];
    float e = emb[idx * 64 + c];
    float d1 = __fsub_rn(e, zv);
    outF[1 + t] = __fadd_rn(zv, d1);
    double s = (double)__fmul_rn(d1, d1);
#pragma unroll
    for (int o = 16; o; o >>= 1) s += __shfl_down_sync(0xffffffffu, s, o);
    __shared__ double ws[32];
    int lane = threadIdx.x & 31, w = threadIdx.x >> 5;
    if (lane == 0) ws[w] = s;
    __syncthreads();
    if (w == 0) {
        double v = ws[lane];
#pragma unroll
        for (int o = 16; o; o >>= 1) v += __shfl_down_sync(0xffffffffu, v, o);
        if (lane == 0) g_partial[blockIdx.x] = v;
    }
}

__global__ void vq_loss(float* __restrict__ outF) {
    __shared__ double sh[256];
    double s = 0.0;
    for (int i = threadIdx.x; i < 2048; i += 256) s += g_partial[i];
    sh[threadIdx.x] = s;
    __syncthreads();
    for (int st = 128; st; st >>= 1) {
        if (threadIdx.x < st) sh[threadIdx.x] += sh[threadIdx.x + st];
        __syncthreads();
    }
    if (threadIdx.x == 0) {
        float m = (float)(sh[0] / (double)NELEM);
        outF[0] = __fadd_rn(m, __fmul_rn(0.25f, m));
    }
}

extern "C" void kernel_launch(void* const* d_in, const int* in_sizes, int n_in,
                              void* d_out, int out_size) {
    const float* z = (const float*)d_in[0];
    const float* emb = (const float*)d_in[1];
    float* out = (float*)d_out;

    cudaFuncSetAttribute(vq_mma, cudaFuncAttributeMaxDynamicSharedMemorySize, SMEM_MMA);

    vq_transpose<<<512, 256>>>(z);
    vq_prep<<<2048, 256>>>(emb);
    vq_mma<<<N_ROWS / 128, 256, SMEM_MMA>>>();
    vq_exact<<<2048, 256>>>(emb);
    vq_finalize<<<32, 1024>>>(out);
    vq_out<<<2048, 1024>>>(z, emb, out);
    vq_loss<<<1, 256>>>(out);
}

// round 8
// speedup vs baseline: 1.4087x; 1.4087x over previous
#include <cuda_runtime.h>
#include <cuda_bf16.h>
#include <cstdint>

#define N_ROWS 32768
#define N_CODES 8192
#define DIM 64
#define HW 4096
#define ZB 262144
#define NELEM 2097152
#define NCH 64
#define TCODES 128
#define CAP (1 << 22)
#define HMARGIN 4.0e-4f

__device__ int                g_idx[N_ROWS];
__device__ float              g_A[N_ROWS];
__device__ float              g_B[N_CODES];
__device__ float              g_zT[N_ROWS * DIM];
__device__ __nv_bfloat16      g_zbf[N_ROWS * DIM];
__device__ __nv_bfloat16      g_ebf[N_CODES * DIM];
__device__ unsigned long long g_key[N_ROWS];
__device__ unsigned int       g_cand[CAP];
__device__ int                g_cnt;
__device__ double             g_partial[2048];

__device__ __forceinline__ uint32_t smem_u32(const void* p) {
    uint32_t a;
    asm("{ .reg .u64 t; cvta.to.shared.u64 t, %1; cvt.u32.u64 %0, t; }" : "=r"(a) : "l"(p));
    return a;
}
__device__ __forceinline__ void cp_async16(uint32_t dst, const void* src) {
    asm volatile("cp.async.cg.shared.global [%0], [%1], 16;" :: "r"(dst), "l"(src) : "memory");
}
#define CP_COMMIT() asm volatile("cp.async.commit_group;" ::: "memory")
#define CP_WAIT1()  asm volatile("cp.async.wait_group 1;" ::: "memory")
#define CP_WAIT0()  asm volatile("cp.async.wait_group 0;" ::: "memory")

__device__ __forceinline__ void mma16816(float& c0, float& c1, float& c2, float& c3,
                                         uint32_t a0, uint32_t a1, uint32_t a2, uint32_t a3,
                                         uint32_t b0, uint32_t b1) {
    asm volatile(
        "mma.sync.aligned.m16n8k16.row.col.f32.bf16.bf16.f32 "
        "{%0,%1,%2,%3}, {%4,%5,%6,%7}, {%8,%9}, {%0,%1,%2,%3};"
        : "+f"(c0), "+f"(c1), "+f"(c2), "+f"(c3)
        : "r"(a0), "r"(a1), "r"(a2), "r"(a3), "r"(b0), "r"(b1));
}
__device__ __forceinline__ void ldmatrix_x4(uint32_t& r0, uint32_t& r1, uint32_t& r2,
                                            uint32_t& r3, uint32_t addr) {
    asm volatile("ldmatrix.sync.aligned.m8n8.x4.shared.b16 {%0,%1,%2,%3}, [%4];"
                 : "=r"(r0), "=r"(r1), "=r"(r2), "=r"(r3) : "r"(addr));
}

// ---------------------------------------------------------------------------
// Transpose z -> zT (f32 row-major), zbf (bf16), A = ||z||^2 (ascending-c fma)
// ---------------------------------------------------------------------------
__global__ void vq_transpose(const float* __restrict__ z) {
    __shared__ float sm[64][65];
    int b = blockIdx.x >> 6;
    int hw0 = (blockIdx.x & 63) << 6;
    int cc = threadIdx.x >> 6, hh = threadIdx.x & 63;
    const float* zb = z + b * ZB + hw0;
#pragma unroll
    for (int cq = 0; cq < 16; cq++) {
        int c = cq * 4 + cc;
        sm[hh][c] = zb[c * HW + hh];
    }
    __syncthreads();
#pragma unroll
    for (int rq = 0; rq < 16; rq++) {
        int r = rq * 4 + cc;
        int n = b * 4096 + hw0 + r;
        float v = sm[r][hh];
        g_zT[n * DIM + hh] = v;
        g_zbf[n * DIM + hh] = __float2bfloat16(v);
    }
    if (threadIdx.x < 64) {
        int r = threadIdx.x;
        float s = 0.f;
#pragma unroll
        for (int c = 0; c < DIM; c++) s = __fmaf_rn(sm[r][c], sm[r][c], s);
        g_A[b * 4096 + hw0 + r] = s;
    }
}

__global__ void vq_prep(const float* __restrict__ emb) {
    int t = blockIdx.x * blockDim.x + threadIdx.x;
    if (t < N_CODES * DIM) g_ebf[t] = __float2bfloat16(emb[t]);
    if (t < N_ROWS) g_key[t] = 0xFFFFFFFFFFFFFFFFull;
    if (t == 0) g_cnt = 0;
    if (t < N_CODES) {
        const float4* ep = (const float4*)(emb + t * DIM);
        float s = 0.f;
#pragma unroll
        for (int i = 0; i < 16; i++) {
            float4 v = ep[i];
            s = __fmaf_rn(v.x, v.x, s);
            s = __fmaf_rn(v.y, v.y, s);
            s = __fmaf_rn(v.z, v.z, s);
            s = __fmaf_rn(v.w, v.w, s);
        }
        g_B[t] = s;
    }
}

// ---------------------------------------------------------------------------
// Filter: bf16 mma.sync dots + running-max candidate collection.
// CTA 256 thr / 8 warps / 128 rows; warp = 16 rows x 128 codes per chunk.
// 3-stage cp.async pipeline (1 sync/chunk), split MMA chains, half-chunk scan.
// ---------------------------------------------------------------------------
#define SMEM_MMA (3 * TCODES * 128)   // 48KB: three 16KB e buffers

__global__ __launch_bounds__(256, 2) void vq_mma(void) {
    extern __shared__ char smc[];
    uint32_t sb = smem_u32(smc);
    int tid = threadIdx.x;
    int lane = tid & 31;
    int wid = tid >> 5;
    int row0 = blockIdx.x * 128;
    int g = lane >> 2, q = lane & 3;

    int rw = row0 + wid * 16;
    int row_a = rw + g, row_b = row_a + 8;
    uint32_t a[4][4];
#pragma unroll
    for (int ks = 0; ks < 4; ks++) {
        const char* pa = (const char*)(g_zbf + row_a * DIM + ks * 16 + q * 2);
        const char* pb = (const char*)(g_zbf + row_b * DIM + ks * 16 + q * 2);
        a[ks][0] = *(const uint32_t*)pa;
        a[ks][1] = *(const uint32_t*)pb;
        a[ks][2] = *(const uint32_t*)(pa + 16);
        a[ks][3] = *(const uint32_t*)(pb + 16);
    }

    uint32_t r8 = (uint32_t)(lane & 7);
    uint32_t h2 = (uint32_t)(lane >> 3);
    uint32_t seg1 = (h2 ^ r8) * 16;
    uint32_t seg2 = ((4 + h2) ^ r8) * 16;
    uint32_t lrow = r8 * 128;

    // prefetch chunks 0,1 (one commit-group each); distance-2 pipeline, 3 bufs
#pragma unroll
    for (int pc = 0; pc < 2; pc++) {
#pragma unroll
        for (int i = 0; i < 4; i++) {
            int s = tid + i * 256;
            int r = s >> 3, seg = s & 7;
            uint32_t off = (uint32_t)(r * 128 + seg * 16);
            uint32_t dst = sb + pc * 16384 + (off ^ ((off >> 3) & 0x70));
            cp_async16(dst, g_ebf + (pc * TCODES + r) * DIM + seg * 8);
        }
        CP_COMMIT();
    }

    const float NEGINF = -__int_as_float(0x7f800000);
    float run0 = NEGINF, run1 = NEGINF;

    int buf = 0;                 // buf = c % 3
    for (int c = 0; c < NCH; c++) {
        if (c < NCH - 1) CP_WAIT1(); else CP_WAIT0();
        __syncthreads();         // all warps done with chunk c-1 -> its buffer is free

        uint32_t ebase = sb + (uint32_t)buf * 16384 + lrow;

        // prefetch chunk c+2 into the buffer chunk c-1 used ((c+2)%3 == (c-1)%3)
        if (c + 2 < NCH) {
            int pbuf = buf - 1; if (pbuf < 0) pbuf = 2;
#pragma unroll
            for (int i = 0; i < 4; i++) {
                int s = tid + i * 256;
                int r = s >> 3, seg = s & 7;
                uint32_t off = (uint32_t)(r * 128 + seg * 16);
                uint32_t dst = sb + (uint32_t)pbuf * 16384 + (off ^ ((off >> 3) & 0x70));
                cp_async16(dst, g_ebf + ((c + 2) * TCODES + r) * DIM + seg * 8);
            }
            CP_COMMIT();
        }

#pragma unroll
        for (int h = 0; h < 2; h++) {
            float acc[8][4];
#pragma unroll
            for (int t = 0; t < 8; t++) {
                uint32_t tb = ebase + (uint32_t)(h * 8 + t) * 1024;
                uint32_t b0, b1, b2, b3, b4, b5, b6, b7;
                ldmatrix_x4(b0, b1, b2, b3, tb + seg1);
                ldmatrix_x4(b4, b5, b6, b7, tb + seg2);
                // two independent 2-deep MMA chains, combined at the end
                float p0 = 0.f, p1 = 0.f, p2 = 0.f, p3 = 0.f;
                float s0 = 0.f, s1 = 0.f, s2 = 0.f, s3 = 0.f;
                mma16816(p0, p1, p2, p3, a[0][0], a[0][1], a[0][2], a[0][3], b0, b1);
                mma16816(s0, s1, s2, s3, a[2][0], a[2][1], a[2][2], a[2][3], b4, b5);
                mma16816(p0, p1, p2, p3, a[1][0], a[1][1], a[1][2], a[1][3], b2, b3);
                mma16816(s0, s1, s2, s3, a[3][0], a[3][1], a[3][2], a[3][3], b6, b7);
                acc[t][0] = p0 + s0; acc[t][1] = p1 + s1;
                acc[t][2] = p2 + s2; acc[t][3] = p3 + s3;
            }

            // per-row half-chunk max
            float m0 = NEGINF, m1 = NEGINF;
#pragma unroll
            for (int t = 0; t < 8; t++) {
                m0 = fmaxf(m0, fmaxf(acc[t][0], acc[t][1]));
                m1 = fmaxf(m1, fmaxf(acc[t][2], acc[t][3]));
            }
            m0 = fmaxf(m0, __shfl_xor_sync(0xffffffffu, m0, 1));
            m0 = fmaxf(m0, __shfl_xor_sync(0xffffffffu, m0, 2));
            m1 = fmaxf(m1, __shfl_xor_sync(0xffffffffu, m1, 1));
            m1 = fmaxf(m1, __shfl_xor_sync(0xffffffffu, m1, 2));
            run0 = fmaxf(run0, m0);
            run1 = fmaxf(run1, m1);
            float thr0 = run0 - HMARGIN, thr1 = run1 - HMARGIN;

            bool anyc = (m0 >= thr0) || (m1 >= thr1);
            if (!__any_sync(0xffffffffu, anyc)) continue;

            int cntl = 0;
#pragma unroll
            for (int t = 0; t < 8; t++) {
                cntl += (acc[t][0] >= thr0);
                cntl += (acc[t][1] >= thr0);
                cntl += (acc[t][2] >= thr1);
                cntl += (acc[t][3] >= thr1);
            }
            int pre = cntl;
#pragma unroll
            for (int o = 1; o < 32; o <<= 1) {
                int v = __shfl_up_sync(0xffffffffu, pre, o);
                if (lane >= o) pre += v;
            }
            int total = __shfl_sync(0xffffffffu, pre, 31);
            int base = 0;
            if (lane == 31 && total) base = atomicAdd(&g_cnt, total);
            base = __shfl_sync(0xffffffffu, base, 31);
            int pos = base + pre - cntl;

            if (cntl) {
                int j0 = c * TCODES + h * 64 + q * 2;
#pragma unroll
                for (int t = 0; t < 8; t++) {
                    int j = j0 + t * 8;
                    if (acc[t][0] >= thr0) { if (pos < CAP) g_cand[pos] = ((unsigned)row_a << 13) | (unsigned)j; pos++; }
                    if (acc[t][1] >= thr0) { if (pos < CAP) g_cand[pos] = ((unsigned)row_a << 13) | (unsigned)(j + 1); pos++; }
                    if (acc[t][2] >= thr1) { if (pos < CAP) g_cand[pos] = ((unsigned)row_b << 13) | (unsigned)j; pos++; }
                    if (acc[t][3] >= thr1) { if (pos < CAP) g_cand[pos] = ((unsigned)row_b << 13) | (unsigned)(j + 1); pos++; }
                }
            }
        }

        buf++; if (buf == 3) buf = 0;
    }
}

// ---------------------------------------------------------------------------
// Exact recheck: reference-matching fp32 d via float4 loads (ascending chain)
// ---------------------------------------------------------------------------
__global__ void vq_exact(const float* __restrict__ emb) {
    int cnt = g_cnt;
    if (cnt > CAP) cnt = CAP;
    for (int i = blockIdx.x * blockDim.x + threadIdx.x; i < cnt; i += gridDim.x * blockDim.x) {
        unsigned u = g_cand[i];
        int n = u >> 13;
        int j = u & 8191;
        const float4* zr = (const float4*)(g_zT + n * DIM);
        const float4* er = (const float4*)(emb + j * DIM);
        float dot = 0.f;
#pragma unroll
        for (int cc = 0; cc < 16; cc++) {
            float4 av = zr[cc];
            float4 bv = er[cc];
            dot = __fmaf_rn(av.x, bv.x, dot);
            dot = __fmaf_rn(av.y, bv.y, dot);
            dot = __fmaf_rn(av.z, bv.z, dot);
            dot = __fmaf_rn(av.w, bv.w, dot);
        }
        float d = __fsub_rn(__fadd_rn(g_A[n], g_B[j]), __fmul_rn(2.0f, dot));
        unsigned long long key = ((unsigned long long)__float_as_uint(d) << 13) | (unsigned)j;
        atomicMin(&g_key[n], key);
    }
}

__global__ void vq_finalize(float* __restrict__ outF) {
    int t = blockIdx.x * blockDim.x + threadIdx.x;
    if (t < N_ROWS) {
        int j = (int)(g_key[t] & 8191ull);
        g_idx[t] = j;
        outF[1 + NELEM + t] = (float)j;
    }
}

__global__ void vq_out(const float* __restrict__ z, const float* __restrict__ emb,
                       float* __restrict__ outF) {
    int t = blockIdx.x * 1024 + threadIdx.x;
    int c = (t >> 12) & 63;
    int n = ((t >> 18) << 12) | (t & 4095);
    int idx = g_idx[n];
    float zv = z[t];
    float e = emb[idx * 64 + c];
    float d1 = __fsub_rn(e, zv);
    outF[1 + t] = __fadd_rn(zv, d1);
    double s = (double)__fmul_rn(d1, d1);
#pragma unroll
    for (int o = 16; o; o >>= 1) s += __shfl_down_sync(0xffffffffu, s, o);
    __shared__ double ws[32];
    int lane = threadIdx.x & 31, w = threadIdx.x >> 5;
    if (lane == 0) ws[w] = s;
    __syncthreads();
    if (w == 0) {
        double v = ws[lane];
#pragma unroll
        for (int o = 16; o; o >>= 1) v += __shfl_down_sync(0xffffffffu, v, o);
        if (lane == 0) g_partial[blockIdx.x] = v;
    }
}

__global__ void vq_loss(float* __restrict__ outF) {
    __shared__ double sh[256];
    double s = 0.0;
    for (int i = threadIdx.x; i < 2048; i += 256) s += g_partial[i];
    sh[threadIdx.x] = s;
    __syncthreads();
    for (int st = 128; st; st >>= 1) {
        if (threadIdx.x < st) sh[threadIdx.x] += sh[threadIdx.x + st];
        __syncthreads();
    }
    if (threadIdx.x == 0) {
        float m = (float)(sh[0] / (double)NELEM);
        outF[0] = __fadd_rn(m, __fmul_rn(0.25f, m));
    }
}

extern "C" void kernel_launch(void* const* d_in, const int* in_sizes, int n_in,
                              void* d_out, int out_size) {
    const float* z = (const float*)d_in[0];
    const float* emb = (const float*)d_in[1];
    float* out = (float*)d_out;

    cudaFuncSetAttribute(vq_mma, cudaFuncAttributeMaxDynamicSharedMemorySize, SMEM_MMA);

    vq_transpose<<<512, 256>>>(z);
    vq_prep<<<2048, 256>>>(emb);
    vq_mma<<<N_ROWS / 128, 256, SMEM_MMA>>>();
    vq_exact<<<2048, 256>>>(emb);
    vq_finalize<<<32, 1024>>>(out);
    vq_out<<<2048, 1024>>>(z, emb, out);
    vq_loss<<<1, 256>>>(out);
}

// round 9
// speedup vs baseline: 1.5040x; 1.0677x over previous
#include <cuda_runtime.h>
#include <cuda_fp16.h>
#include <cstdint>

#define N_ROWS 32768
#define N_CODES 8192
#define DIM 64
#define HW 4096
#define ZB 262144
#define NELEM 2097152
#define NCH 64
#define TCODES 128
#define CAP (1 << 22)
#define HMARGIN 4.5e-4f

__device__ int                g_idx[N_ROWS];
__device__ float              g_A[N_ROWS];
__device__ float              g_B[N_CODES];
__device__ float              g_zT[N_ROWS * DIM];
__device__ __half             g_zh[N_ROWS * DIM];
__device__ __half             g_eh[N_CODES * DIM];
__device__ unsigned long long g_key[N_ROWS];
__device__ unsigned int       g_cand[CAP];
__device__ int                g_cnt;
__device__ double             g_partial[2048];

__device__ __forceinline__ uint32_t smem_u32(const void* p) {
    uint32_t a;
    asm("{ .reg .u64 t; cvta.to.shared.u64 t, %1; cvt.u32.u64 %0, t; }" : "=r"(a) : "l"(p));
    return a;
}
__device__ __forceinline__ void cp_async16(uint32_t dst, const void* src) {
    asm volatile("cp.async.cg.shared.global [%0], [%1], 16;" :: "r"(dst), "l"(src) : "memory");
}
#define CP_COMMIT() asm volatile("cp.async.commit_group;" ::: "memory")
#define CP_WAIT1()  asm volatile("cp.async.wait_group 1;" ::: "memory")
#define CP_WAIT0()  asm volatile("cp.async.wait_group 0;" ::: "memory")

// f16 x f16 -> f16 accumulate (2 accum regs)
__device__ __forceinline__ void mma16816h(uint32_t& c0, uint32_t& c1,
                                          uint32_t a0, uint32_t a1, uint32_t a2, uint32_t a3,
                                          uint32_t b0, uint32_t b1) {
    asm volatile(
        "mma.sync.aligned.m16n8k16.row.col.f16.f16.f16.f16 "
        "{%0,%1}, {%2,%3,%4,%5}, {%6,%7}, {%0,%1};"
        : "+r"(c0), "+r"(c1)
        : "r"(a0), "r"(a1), "r"(a2), "r"(a3), "r"(b0), "r"(b1));
}
__device__ __forceinline__ void ldmatrix_x4(uint32_t& r0, uint32_t& r1, uint32_t& r2,
                                            uint32_t& r3, uint32_t addr) {
    asm volatile("ldmatrix.sync.aligned.m8n8.x4.shared.b16 {%0,%1,%2,%3}, [%4];"
                 : "=r"(r0), "=r"(r1), "=r"(r2), "=r"(r3) : "r"(addr));
}
__device__ __forceinline__ __half2 u2h(uint32_t v) {
    return reinterpret_cast<__half2&>(v);
}

// ---------------------------------------------------------------------------
// Transpose z -> zT (f32 row-major), zh (fp16), A = ||z||^2 (ascending-c fma)
// ---------------------------------------------------------------------------
__global__ void vq_transpose(const float* __restrict__ z) {
    __shared__ float sm[64][65];
    int b = blockIdx.x >> 6;
    int hw0 = (blockIdx.x & 63) << 6;
    int cc = threadIdx.x >> 6, hh = threadIdx.x & 63;
    const float* zb = z + b * ZB + hw0;
#pragma unroll
    for (int cq = 0; cq < 16; cq++) {
        int c = cq * 4 + cc;
        sm[hh][c] = zb[c * HW + hh];
    }
    __syncthreads();
#pragma unroll
    for (int rq = 0; rq < 16; rq++) {
        int r = rq * 4 + cc;
        int n = b * 4096 + hw0 + r;
        float v = sm[r][hh];
        g_zT[n * DIM + hh] = v;
        g_zh[n * DIM + hh] = __float2half(v);
    }
    if (threadIdx.x < 64) {
        int r = threadIdx.x;
        float s = 0.f;
#pragma unroll
        for (int c = 0; c < DIM; c++) s = __fmaf_rn(sm[r][c], sm[r][c], s);
        g_A[b * 4096 + hw0 + r] = s;
    }
}

__global__ void vq_prep(const float* __restrict__ emb) {
    int t = blockIdx.x * blockDim.x + threadIdx.x;
    if (t < N_CODES * DIM) g_eh[t] = __float2half(emb[t]);
    if (t < N_ROWS) g_key[t] = 0xFFFFFFFFFFFFFFFFull;
    if (t == 0) g_cnt = 0;
    if (t < N_CODES) {
        const float4* ep = (const float4*)(emb + t * DIM);
        float s = 0.f;
#pragma unroll
        for (int i = 0; i < 16; i++) {
            float4 v = ep[i];
            s = __fmaf_rn(v.x, v.x, s);
            s = __fmaf_rn(v.y, v.y, s);
            s = __fmaf_rn(v.z, v.z, s);
            s = __fmaf_rn(v.w, v.w, s);
        }
        g_B[t] = s;
    }
}

// no-op spacer so vq_mma lands in the ncu-captured (4th) launch slot
__global__ void vq_probe(void) {}

// ---------------------------------------------------------------------------
// Filter: fp16 mma.sync (f16 accumulate) + running-max candidate collection.
// CTA 256 thr / 8 warps / 128 rows; warp = 16 rows x 128 codes per chunk.
// ---------------------------------------------------------------------------
#define SMEM_MMA (3 * TCODES * 128)   // three 16KB e buffers

__global__ __launch_bounds__(256, 2) void vq_mma(void) {
    extern __shared__ char smc[];
    uint32_t sb = smem_u32(smc);
    int tid = threadIdx.x;
    int lane = tid & 31;
    int wid = tid >> 5;
    int row0 = blockIdx.x * 128;
    int g = lane >> 2, q = lane & 3;

    int rw = row0 + wid * 16;
    int row_a = rw + g, row_b = row_a + 8;
    uint32_t a[4][4];
#pragma unroll
    for (int ks = 0; ks < 4; ks++) {
        const char* pa = (const char*)(g_zh + row_a * DIM + ks * 16 + q * 2);
        const char* pb = (const char*)(g_zh + row_b * DIM + ks * 16 + q * 2);
        a[ks][0] = *(const uint32_t*)pa;
        a[ks][1] = *(const uint32_t*)pb;
        a[ks][2] = *(const uint32_t*)(pa + 16);
        a[ks][3] = *(const uint32_t*)(pb + 16);
    }

    uint32_t r8 = (uint32_t)(lane & 7);
    uint32_t h2 = (uint32_t)(lane >> 3);
    uint32_t seg1 = (h2 ^ r8) * 16;
    uint32_t seg2 = ((4 + h2) ^ r8) * 16;
    uint32_t lrow = r8 * 128;

#pragma unroll
    for (int pc = 0; pc < 2; pc++) {
#pragma unroll
        for (int i = 0; i < 4; i++) {
            int s = tid + i * 256;
            int r = s >> 3, seg = s & 7;
            uint32_t off = (uint32_t)(r * 128 + seg * 16);
            uint32_t dst = sb + pc * 16384 + (off ^ ((off >> 3) & 0x70));
            cp_async16(dst, g_eh + (pc * TCODES + r) * DIM + seg * 8);
        }
        CP_COMMIT();
    }

    const float NEGINF = -__int_as_float(0x7f800000);
    float run0 = NEGINF, run1 = NEGINF;

    int buf = 0;
    for (int c = 0; c < NCH; c++) {
        if (c < NCH - 1) CP_WAIT1(); else CP_WAIT0();
        __syncthreads();

        uint32_t ebase = sb + (uint32_t)buf * 16384 + lrow;

        if (c + 2 < NCH) {
            int pbuf = buf - 1; if (pbuf < 0) pbuf = 2;
#pragma unroll
            for (int i = 0; i < 4; i++) {
                int s = tid + i * 256;
                int r = s >> 3, seg = s & 7;
                uint32_t off = (uint32_t)(r * 128 + seg * 16);
                uint32_t dst = sb + (uint32_t)pbuf * 16384 + (off ^ ((off >> 3) & 0x70));
                cp_async16(dst, g_eh + ((c + 2) * TCODES + r) * DIM + seg * 8);
            }
            CP_COMMIT();
        }

#pragma unroll
        for (int h = 0; h < 2; h++) {
            __half2 acc_a[8], acc_b[8];
#pragma unroll
            for (int t = 0; t < 8; t++) {
                uint32_t tb = ebase + (uint32_t)(h * 8 + t) * 1024;
                uint32_t b0, b1, b2, b3, b4, b5, b6, b7;
                ldmatrix_x4(b0, b1, b2, b3, tb + seg1);
                ldmatrix_x4(b4, b5, b6, b7, tb + seg2);
                uint32_t p0 = 0, p1 = 0, s0 = 0, s1 = 0;
                mma16816h(p0, p1, a[0][0], a[0][1], a[0][2], a[0][3], b0, b1);
                mma16816h(s0, s1, a[2][0], a[2][1], a[2][2], a[2][3], b4, b5);
                mma16816h(p0, p1, a[1][0], a[1][1], a[1][2], a[1][3], b2, b3);
                mma16816h(s0, s1, a[3][0], a[3][1], a[3][2], a[3][3], b6, b7);
                acc_a[t] = __hadd2(u2h(p0), u2h(s0));   // rows row_a, cols 2q,2q+1
                acc_b[t] = __hadd2(u2h(p1), u2h(s1));   // rows row_b
            }

            // per-row half-chunk max (vector fp16 then scalar)
            __half2 hm0 = acc_a[0], hm1 = acc_b[0];
#pragma unroll
            for (int t = 1; t < 8; t++) {
                hm0 = __hmax2(hm0, acc_a[t]);
                hm1 = __hmax2(hm1, acc_b[t]);
            }
            float m0 = fmaxf(__low2float(hm0), __high2float(hm0));
            float m1 = fmaxf(__low2float(hm1), __high2float(hm1));
            m0 = fmaxf(m0, __shfl_xor_sync(0xffffffffu, m0, 1));
            m0 = fmaxf(m0, __shfl_xor_sync(0xffffffffu, m0, 2));
            m1 = fmaxf(m1, __shfl_xor_sync(0xffffffffu, m1, 1));
            m1 = fmaxf(m1, __shfl_xor_sync(0xffffffffu, m1, 2));
            run0 = fmaxf(run0, m0);
            run1 = fmaxf(run1, m1);
            float thr0f = run0 - HMARGIN, thr1f = run1 - HMARGIN;

            bool anyc = (m0 >= thr0f) || (m1 >= thr1f);
            if (!__any_sync(0xffffffffu, anyc)) continue;

            // half-domain thresholds, biased down so compare is a superset
            __half2 thr0 = __float2half2_rn(thr0f - 2e-5f);
            __half2 thr1 = __float2half2_rn(thr1f - 2e-5f);

            __half2 cnt2 = __float2half2_rn(0.f);
#pragma unroll
            for (int t = 0; t < 8; t++) {
                cnt2 = __hadd2(cnt2, __hge2(acc_a[t], thr0));
                cnt2 = __hadd2(cnt2, __hge2(acc_b[t], thr1));
            }
            int cntl = (int)(__low2float(cnt2) + __high2float(cnt2));

            int pre = cntl;
#pragma unroll
            for (int o = 1; o < 32; o <<= 1) {
                int v = __shfl_up_sync(0xffffffffu, pre, o);
                if (lane >= o) pre += v;
            }
            int total = __shfl_sync(0xffffffffu, pre, 31);
            int base = 0;
            if (lane == 31 && total) base = atomicAdd(&g_cnt, total);
            base = __shfl_sync(0xffffffffu, base, 31);
            int pos = base + pre - cntl;

            if (cntl) {
                int j0 = c * TCODES + h * 64 + q * 2;
#pragma unroll
                for (int t = 0; t < 8; t++) {
                    int j = j0 + t * 8;
                    __half2 ra = __hge2(acc_a[t], thr0);
                    __half2 rb = __hge2(acc_b[t], thr1);
                    uint32_t ma = reinterpret_cast<uint32_t&>(ra);
                    uint32_t mb = reinterpret_cast<uint32_t&>(rb);
                    if (ma & 0xFFFFu) { if (pos < CAP) g_cand[pos] = ((unsigned)row_a << 13) | (unsigned)j; pos++; }
                    if (ma >> 16)     { if (pos < CAP) g_cand[pos] = ((unsigned)row_a << 13) | (unsigned)(j + 1); pos++; }
                    if (mb & 0xFFFFu) { if (pos < CAP) g_cand[pos] = ((unsigned)row_b << 13) | (unsigned)j; pos++; }
                    if (mb >> 16)     { if (pos < CAP) g_cand[pos] = ((unsigned)row_b << 13) | (unsigned)(j + 1); pos++; }
                }
            }
        }

        buf++; if (buf == 3) buf = 0;
    }
}

// ---------------------------------------------------------------------------
// Exact recheck: reference-matching fp32 d via float4 loads (ascending chain)
// ---------------------------------------------------------------------------
__global__ void vq_exact(const float* __restrict__ emb) {
    int cnt = g_cnt;
    if (cnt > CAP) cnt = CAP;
    for (int i = blockIdx.x * blockDim.x + threadIdx.x; i < cnt; i += gridDim.x * blockDim.x) {
        unsigned u = g_cand[i];
        int n = u >> 13;
        int j = u & 8191;
        const float4* zr = (const float4*)(g_zT + n * DIM);
        const float4* er = (const float4*)(emb + j * DIM);
        float dot = 0.f;
#pragma unroll
        for (int cc = 0; cc < 16; cc++) {
            float4 av = zr[cc];
            float4 bv = er[cc];
            dot = __fmaf_rn(av.x, bv.x, dot);
            dot = __fmaf_rn(av.y, bv.y, dot);
            dot = __fmaf_rn(av.z, bv.z, dot);
            dot = __fmaf_rn(av.w, bv.w, dot);
        }
        float d = __fsub_rn(__fadd_rn(g_A[n], g_B[j]), __fmul_rn(2.0f, dot));
        unsigned long long key = ((unsigned long long)__float_as_uint(d) << 13) | (unsigned)j;
        atomicMin(&g_key[n], key);
    }
}

__global__ void vq_finalize(float* __restrict__ outF) {
    int t = blockIdx.x * blockDim.x + threadIdx.x;
    if (t < N_ROWS) {
        int j = (int)(g_key[t] & 8191ull);
        g_idx[t] = j;
        outF[1 + NELEM + t] = (float)j;
    }
}

__global__ void vq_out(const float* __restrict__ z, const float* __restrict__ emb,
                       float* __restrict__ outF) {
    int t = blockIdx.x * 1024 + threadIdx.x;
    int c = (t >> 12) & 63;
    int n = ((t >> 18) << 12) | (t & 4095);
    int idx = g_idx[n];
    float zv = z[t];
    float e = emb[idx * 64 + c];
    float d1 = __fsub_rn(e, zv);
    outF[1 + t] = __fadd_rn(zv, d1);
    double s = (double)__fmul_rn(d1, d1);
#pragma unroll
    for (int o = 16; o; o >>= 1) s += __shfl_down_sync(0xffffffffu, s, o);
    __shared__ double ws[32];
    int lane = threadIdx.x & 31, w = threadIdx.x >> 5;
    if (lane == 0) ws[w] = s;
    __syncthreads();
    if (w == 0) {
        double v = ws[lane];
#pragma unroll
        for (int o = 16; o; o >>= 1) v += __shfl_down_sync(0xffffffffu, v, o);
        if (lane == 0) g_partial[blockIdx.x] = v;
    }
}

__global__ void vq_loss(float* __restrict__ outF) {
    __shared__ double sh[256];
    double s = 0.0;
    for (int i = threadIdx.x; i < 2048; i += 256) s += g_partial[i];
    sh[threadIdx.x] = s;
    __syncthreads();
    for (int st = 128; st; st >>= 1) {
        if (threadIdx.x < st) sh[threadIdx.x] += sh[threadIdx.x + st];
        __syncthreads();
    }
    if (threadIdx.x == 0) {
        float m = (float)(sh[0] / (double)NELEM);
        outF[0] = __fadd_rn(m, __fmul_rn(0.25f, m));
    }
}

extern "C" void kernel_launch(void* const* d_in, const int* in_sizes, int n_in,
                              void* d_out, int out_size) {
    const float* z = (const float*)d_in[0];
    const float* emb = (const float*)d_in[1];
    float* out = (float*)d_out;

    cudaFuncSetAttribute(vq_mma, cudaFuncAttributeMaxDynamicSharedMemorySize, SMEM_MMA);

    vq_transpose<<<512, 256>>>(z);
    vq_prep<<<2048, 256>>>(emb);
    vq_probe<<<1, 32>>>();                       // spacer: puts vq_mma in ncu slot
    vq_mma<<<N_ROWS / 128, 256, SMEM_MMA>>>();
    vq_exact<<<2048, 256>>>(emb);
    vq_finalize<<<32, 1024>>>(out);
    vq_out<<<2048, 1024>>>(z, emb, out);
    vq_loss<<<1, 256>>>(out);
}

// round 10
// speedup vs baseline: 1.7701x; 1.1769x over previous
#include <cuda_runtime.h>
#include <cuda_fp16.h>
#include <cstdint>

#define N_ROWS 32768
#define N_CODES 8192
#define DIM 64
#define HW 4096
#define ZB 262144
#define NELEM 2097152
#define NCH 64
#define TCODES 128
#define CAP (1 << 22)
#define HMARGIN 4.5e-4f

__device__ int                g_idx[N_ROWS];
__device__ float              g_A[N_ROWS];
__device__ float              g_B[N_CODES];
__device__ float              g_zT[N_ROWS * DIM];
__device__ __half             g_zh[N_ROWS * DIM];
__device__ __half             g_eh[N_CODES * DIM];
__device__ unsigned long long g_key[N_ROWS];
__device__ unsigned int       g_cand[CAP];
__device__ int                g_cnt;
__device__ double             g_partial[2048];

__device__ __forceinline__ uint32_t smem_u32(const void* p) {
    uint32_t a;
    asm("{ .reg .u64 t; cvta.to.shared.u64 t, %1; cvt.u32.u64 %0, t; }" : "=r"(a) : "l"(p));
    return a;
}
__device__ __forceinline__ void cp_async16(uint32_t dst, const void* src) {
    asm volatile("cp.async.cg.shared.global [%0], [%1], 16;" :: "r"(dst), "l"(src) : "memory");
}
#define CP_COMMIT() asm volatile("cp.async.commit_group;" ::: "memory")
#define CP_WAIT1()  asm volatile("cp.async.wait_group 1;" ::: "memory")
#define CP_WAIT0()  asm volatile("cp.async.wait_group 0;" ::: "memory")

__device__ __forceinline__ void mma16816h(uint32_t& c0, uint32_t& c1,
                                          uint32_t a0, uint32_t a1, uint32_t a2, uint32_t a3,
                                          uint32_t b0, uint32_t b1) {
    asm volatile(
        "mma.sync.aligned.m16n8k16.row.col.f16.f16.f16.f16 "
        "{%0,%1}, {%2,%3,%4,%5}, {%6,%7}, {%0,%1};"
        : "+r"(c0), "+r"(c1)
        : "r"(a0), "r"(a1), "r"(a2), "r"(a3), "r"(b0), "r"(b1));
}
__device__ __forceinline__ void ldmatrix_x4(uint32_t& r0, uint32_t& r1, uint32_t& r2,
                                            uint32_t& r3, uint32_t addr) {
    asm volatile("ldmatrix.sync.aligned.m8n8.x4.shared.b16 {%0,%1,%2,%3}, [%4];"
                 : "=r"(r0), "=r"(r1), "=r"(r2), "=r"(r3) : "r"(addr));
}
__device__ __forceinline__ __half2 u2h(uint32_t v) {
    return reinterpret_cast<__half2&>(v);
}

// ---------------------------------------------------------------------------
// Transpose z -> zT (f32 row-major), zh (fp16), A = ||z||^2 (ascending-c fma)
// ---------------------------------------------------------------------------
__global__ void vq_transpose(const float* __restrict__ z) {
    __shared__ float sm[64][65];
    int b = blockIdx.x >> 6;
    int hw0 = (blockIdx.x & 63) << 6;
    int cc = threadIdx.x >> 6, hh = threadIdx.x & 63;
    const float* zb = z + b * ZB + hw0;
#pragma unroll
    for (int cq = 0; cq < 16; cq++) {
        int c = cq * 4 + cc;
        sm[hh][c] = zb[c * HW + hh];
    }
    __syncthreads();
#pragma unroll
    for (int rq = 0; rq < 16; rq++) {
        int r = rq * 4 + cc;
        int n = b * 4096 + hw0 + r;
        float v = sm[r][hh];
        g_zT[n * DIM + hh] = v;
        g_zh[n * DIM + hh] = __float2half(v);
    }
    if (threadIdx.x < 64) {
        int r = threadIdx.x;
        float s = 0.f;
#pragma unroll
        for (int c = 0; c < DIM; c++) s = __fmaf_rn(sm[r][c], sm[r][c], s);
        g_A[b * 4096 + hw0 + r] = s;
    }
}

__global__ void vq_prep(const float* __restrict__ emb) {
    int t = blockIdx.x * blockDim.x + threadIdx.x;
    if (t < N_CODES * DIM) g_eh[t] = __float2half(emb[t]);
    if (t < N_ROWS) g_key[t] = 0xFFFFFFFFFFFFFFFFull;
    if (t == 0) g_cnt = 0;
    if (t < N_CODES) {
        const float4* ep = (const float4*)(emb + t * DIM);
        float s = 0.f;
#pragma unroll
        for (int i = 0; i < 16; i++) {
            float4 v = ep[i];
            s = __fmaf_rn(v.x, v.x, s);
            s = __fmaf_rn(v.y, v.y, s);
            s = __fmaf_rn(v.z, v.z, s);
            s = __fmaf_rn(v.w, v.w, s);
        }
        g_B[t] = s;
    }
}

// no-op spacer so vq_mma lands in the ncu-captured (4th) launch slot
__global__ void vq_probe(void) {}

// ---------------------------------------------------------------------------
// Filter: fp16 mma.sync (f16 accumulate) + running-max candidate collection.
// CTA 256 thr / 8 warps / 128 rows; warp = 16 rows x 128 codes per chunk.
// Hand-pipelined LDSM (next tile's B issued before current HMMAs),
// mask-based candidate emission.
// ---------------------------------------------------------------------------
#define SMEM_MMA (3 * TCODES * 128)   // three 16KB e buffers

__global__ __launch_bounds__(256, 2) void vq_mma(void) {
    extern __shared__ char smc[];
    uint32_t sb = smem_u32(smc);
    int tid = threadIdx.x;
    int lane = tid & 31;
    int wid = tid >> 5;
    int row0 = blockIdx.x * 128;
    int g = lane >> 2, q = lane & 3;

    int rw = row0 + wid * 16;
    int row_a = rw + g, row_b = row_a + 8;
    uint32_t a[4][4];
#pragma unroll
    for (int ks = 0; ks < 4; ks++) {
        const char* pa = (const char*)(g_zh + row_a * DIM + ks * 16 + q * 2);
        const char* pb = (const char*)(g_zh + row_b * DIM + ks * 16 + q * 2);
        a[ks][0] = *(const uint32_t*)pa;
        a[ks][1] = *(const uint32_t*)pb;
        a[ks][2] = *(const uint32_t*)(pa + 16);
        a[ks][3] = *(const uint32_t*)(pb + 16);
    }

    uint32_t r8 = (uint32_t)(lane & 7);
    uint32_t h2 = (uint32_t)(lane >> 3);
    uint32_t seg1 = (h2 ^ r8) * 16;
    uint32_t seg2 = ((4 + h2) ^ r8) * 16;
    uint32_t lrow = r8 * 128;

#pragma unroll
    for (int pc = 0; pc < 2; pc++) {
#pragma unroll
        for (int i = 0; i < 4; i++) {
            int s = tid + i * 256;
            int r = s >> 3, seg = s & 7;
            uint32_t off = (uint32_t)(r * 128 + seg * 16);
            uint32_t dst = sb + pc * 16384 + (off ^ ((off >> 3) & 0x70));
            cp_async16(dst, g_eh + (pc * TCODES + r) * DIM + seg * 8);
        }
        CP_COMMIT();
    }

    const float NEGINF = -__int_as_float(0x7f800000);
    float run0 = NEGINF, run1 = NEGINF;

    int buf = 0;
    for (int c = 0; c < NCH; c++) {
        if (c < NCH - 1) CP_WAIT1(); else CP_WAIT0();
        __syncthreads();

        uint32_t ebase = sb + (uint32_t)buf * 16384 + lrow;

        if (c + 2 < NCH) {
            int pbuf = buf - 1; if (pbuf < 0) pbuf = 2;
#pragma unroll
            for (int i = 0; i < 4; i++) {
                int s = tid + i * 256;
                int r = s >> 3, seg = s & 7;
                uint32_t off = (uint32_t)(r * 128 + seg * 16);
                uint32_t dst = sb + (uint32_t)pbuf * 16384 + (off ^ ((off >> 3) & 0x70));
                cp_async16(dst, g_eh + ((c + 2) * TCODES + r) * DIM + seg * 8);
            }
            CP_COMMIT();
        }

#pragma unroll
        for (int h = 0; h < 2; h++) {
            __half2 acc_a[8], acc_b[8];
            uint32_t hbase = ebase + (uint32_t)(h * 8) * 1024;

            // software pipeline: B regs for tile t loaded before HMMAs of t-1 finish
            uint32_t bA0, bA1, bA2, bA3, bB0, bB1, bB2, bB3;
            ldmatrix_x4(bA0, bA1, bA2, bA3, hbase + seg1);
            ldmatrix_x4(bB0, bB1, bB2, bB3, hbase + seg2);

#pragma unroll
            for (int t = 0; t < 8; t++) {
                uint32_t nA0, nA1, nA2, nA3, nB0, nB1, nB2, nB3;
                if (t < 7) {
                    uint32_t tb = hbase + (uint32_t)(t + 1) * 1024;
                    ldmatrix_x4(nA0, nA1, nA2, nA3, tb + seg1);
                    ldmatrix_x4(nB0, nB1, nB2, nB3, tb + seg2);
                }
                uint32_t p0 = 0, p1 = 0, s0 = 0, s1 = 0;
                mma16816h(p0, p1, a[0][0], a[0][1], a[0][2], a[0][3], bA0, bA1);
                mma16816h(s0, s1, a[2][0], a[2][1], a[2][2], a[2][3], bB0, bB1);
                mma16816h(p0, p1, a[1][0], a[1][1], a[1][2], a[1][3], bA2, bA3);
                mma16816h(s0, s1, a[3][0], a[3][1], a[3][2], a[3][3], bB2, bB3);
                acc_a[t] = __hadd2(u2h(p0), u2h(s0));
                acc_b[t] = __hadd2(u2h(p1), u2h(s1));
                if (t < 7) {
                    bA0 = nA0; bA1 = nA1; bA2 = nA2; bA3 = nA3;
                    bB0 = nB0; bB1 = nB1; bB2 = nB2; bB3 = nB3;
                }
            }

            // per-row half-chunk max
            __half2 hm0 = acc_a[0], hm1 = acc_b[0];
#pragma unroll
            for (int t = 1; t < 8; t++) {
                hm0 = __hmax2(hm0, acc_a[t]);
                hm1 = __hmax2(hm1, acc_b[t]);
            }
            float m0 = fmaxf(__low2float(hm0), __high2float(hm0));
            float m1 = fmaxf(__low2float(hm1), __high2float(hm1));
            m0 = fmaxf(m0, __shfl_xor_sync(0xffffffffu, m0, 1));
            m0 = fmaxf(m0, __shfl_xor_sync(0xffffffffu, m0, 2));
            m1 = fmaxf(m1, __shfl_xor_sync(0xffffffffu, m1, 1));
            m1 = fmaxf(m1, __shfl_xor_sync(0xffffffffu, m1, 2));
            run0 = fmaxf(run0, m0);
            run1 = fmaxf(run1, m1);
            float thr0f = run0 - HMARGIN, thr1f = run1 - HMARGIN;

            bool anyc = (m0 >= thr0f) || (m1 >= thr1f);
            if (!__any_sync(0xffffffffu, anyc)) continue;

            // half-domain thresholds, biased down so compare is a superset
            __half2 thr0 = __float2half2_rn(thr0f - 2e-5f);
            __half2 thr1 = __float2half2_rn(thr1f - 2e-5f);

            // build 32-bit candidate mask: bits [2t+odd] rows_a, [16+2t+odd] rows_b
            uint32_t mask = 0;
#pragma unroll
            for (int t = 0; t < 8; t++) {
                unsigned ma = __hge2_mask(acc_a[t], thr0);
                unsigned mb = __hge2_mask(acc_b[t], thr1);
                mask |= ((ma & 1u) | ((ma >> 15) & 2u)) << (2 * t);
                mask |= (((mb & 1u) | ((mb >> 15) & 2u)) << (2 * t)) << 16;
            }

            int cntl = __popc(mask);
            int pre = cntl;
#pragma unroll
            for (int o = 1; o < 32; o <<= 1) {
                int v = __shfl_up_sync(0xffffffffu, pre, o);
                if (lane >= o) pre += v;
            }
            int total = __shfl_sync(0xffffffffu, pre, 31);
            int base = 0;
            if (lane == 31 && total) base = atomicAdd(&g_cnt, total);
            base = __shfl_sync(0xffffffffu, base, 31);
            int pos = base + pre - cntl;

            int j0 = c * TCODES + h * 64 + q * 2;
            while (mask) {
                int bi = __ffs(mask) - 1;
                mask &= mask - 1;
                int row = (bi < 16) ? row_a : row_b;
                int j = j0 + ((bi & 15) >> 1) * 8 + (bi & 1);
                if (pos < CAP) g_cand[pos] = ((unsigned)row << 13) | (unsigned)j;
                pos++;
            }
        }

        buf++; if (buf == 3) buf = 0;
    }
}

// ---------------------------------------------------------------------------
// Exact recheck: reference-matching fp32 d via float4 loads (ascending chain)
// ---------------------------------------------------------------------------
__global__ void vq_exact(const float* __restrict__ emb) {
    int cnt = g_cnt;
    if (cnt > CAP) cnt = CAP;
    for (int i = blockIdx.x * blockDim.x + threadIdx.x; i < cnt; i += gridDim.x * blockDim.x) {
        unsigned u = g_cand[i];
        int n = u >> 13;
        int j = u & 8191;
        const float4* zr = (const float4*)(g_zT + n * DIM);
        const float4* er = (const float4*)(emb + j * DIM);
        float dot = 0.f;
#pragma unroll
        for (int cc = 0; cc < 16; cc++) {
            float4 av = zr[cc];
            float4 bv = er[cc];
            dot = __fmaf_rn(av.x, bv.x, dot);
            dot = __fmaf_rn(av.y, bv.y, dot);
            dot = __fmaf_rn(av.z, bv.z, dot);
            dot = __fmaf_rn(av.w, bv.w, dot);
        }
        float d = __fsub_rn(__fadd_rn(g_A[n], g_B[j]), __fmul_rn(2.0f, dot));
        unsigned long long key = ((unsigned long long)__float_as_uint(d) << 13) | (unsigned)j;
        atomicMin(&g_key[n], key);
    }
}

__global__ void vq_finalize(float* __restrict__ outF) {
    int t = blockIdx.x * blockDim.x + threadIdx.x;
    if (t < N_ROWS) {
        int j = (int)(g_key[t] & 8191ull);
        g_idx[t] = j;
        outF[1 + NELEM + t] = (float)j;
    }
}

__global__ void vq_out(const float* __restrict__ z, const float* __restrict__ emb,
                       float* __restrict__ outF) {
    int t = blockIdx.x * 1024 + threadIdx.x;
    int c = (t >> 12) & 63;
    int n = ((t >> 18) << 12) | (t & 4095);
    int idx = g_idx[n];
    float zv = z[t];
    float e = emb[idx * 64 + c];
    float d1 = __fsub_rn(e, zv);
    outF[1 + t] = __fadd_rn(zv, d1);
    double s = (double)__fmul_rn(d1, d1);
#pragma unroll
    for (int o = 16; o; o >>= 1) s += __shfl_down_sync(0xffffffffu, s, o);
    __shared__ double ws[32];
    int lane = threadIdx.x & 31, w = threadIdx.x >> 5;
    if (lane == 0) ws[w] = s;
    __syncthreads();
    if (w == 0) {
        double v = ws[lane];
#pragma unroll
        for (int o = 16; o; o >>= 1) v += __shfl_down_sync(0xffffffffu, v, o);
        if (lane == 0) g_partial[blockIdx.x] = v;
    }
}

__global__ void vq_loss(float* __restrict__ outF) {
    __shared__ double sh[256];
    double s = 0.0;
    for (int i = threadIdx.x; i < 2048; i += 256) s += g_partial[i];
    sh[threadIdx.x] = s;
    __syncthreads();
    for (int st = 128; st; st >>= 1) {
        if (threadIdx.x < st) sh[threadIdx.x] += sh[threadIdx.x + st];
        __syncthreads();
    }
    if (threadIdx.x == 0) {
        float m = (float)(sh[0] / (double)NELEM);
        outF[0] = __fadd_rn(m, __fmul_rn(0.25f, m));
    }
}

extern "C" void kernel_launch(void* const* d_in, const int* in_sizes, int n_in,
                              void* d_out, int out_size) {
    const float* z = (const float*)d_in[0];
    const float* emb = (const float*)d_in[1];
    float* out = (float*)d_out;

    cudaFuncSetAttribute(vq_mma, cudaFuncAttributeMaxDynamicSharedMemorySize, SMEM_MMA);

    vq_transpose<<<512, 256>>>(z);
    vq_prep<<<2048, 256>>>(emb);
    vq_probe<<<1, 32>>>();                       // spacer: keeps vq_mma in ncu slot
    vq_mma<<<N_ROWS / 128, 256, SMEM_MMA>>>();
    vq_exact<<<2048, 256>>>(emb);
    vq_finalize<<<32, 1024>>>(out);
    vq_out<<<2048, 1024>>>(z, emb, out);
    vq_loss<<<1, 256>>>(out);
}